// round 13
// baseline (speedup 1.0000x reference)
#include <cuda_runtime.h>
#include <cuda_fp16.h>
#include <math.h>

#define NMAX   50000
#define EMAX   400000
#define D      64
#define DD     128
#define NBND   64
#define NROWS  65

// Device scratch (zero-init at load; replay-deterministic: setup re-zeroes
// g_acc/g_accs each call, gemm re-zeroes din/dout each call)
__device__ __align__(16) float   g_acc[NMAX * DD];
__device__ float  g_accs[NMAX];
__device__ int    g_din[NMAX];
__device__ int    g_dout[NMAX];
__device__ __align__(16) __half2 g_feath[NMAX * 32];
__device__ __align__(16) __half  g_t2h[NROWS * D];

__device__ __forceinline__ void red_add_v4(float* p, float4 v) {
    asm volatile("red.global.add.v4.f32 [%0], {%1, %2, %3, %4};"
                 :: "l"(p), "f"(v.x), "f"(v.y), "f"(v.z), "f"(v.w)
                 : "memory");
}

__device__ __forceinline__ void fmaf2(unsigned long long& c,
                                      unsigned long long a,
                                      unsigned long long b) {
    asm("fma.rn.f32x2 %0, %1, %2, %0;" : "+l"(c) : "l"(a), "l"(b));
}

__device__ __forceinline__ void acc_prod(uint4 tv, uint4 fv, float4& ca, float4& cb) {
    const __half2* th = (const __half2*)&tv;
    const __half2* fh = (const __half2*)&fv;
    float2 t0 = __half22float2(th[0]), f0 = __half22float2(fh[0]);
    float2 t1 = __half22float2(th[1]), f1 = __half22float2(fh[1]);
    float2 t2 = __half22float2(th[2]), f2 = __half22float2(fh[2]);
    float2 t3 = __half22float2(th[3]), f3 = __half22float2(fh[3]);
    ca.x = fmaf(t0.x, f0.x, ca.x); ca.y = fmaf(t0.y, f0.y, ca.y);
    ca.z = fmaf(t1.x, f1.x, ca.z); ca.w = fmaf(t1.y, f1.y, ca.w);
    cb.x = fmaf(t2.x, f2.x, cb.x); cb.y = fmaf(t2.y, f2.y, cb.y);
    cb.z = fmaf(t3.x, f3.x, cb.z); cb.w = fmaf(t3.y, f3.y, cb.w);
}

// ---------------------------------------------------------------------------
// 0) setup v2: wide, low-instruction-overhead version.
//    - g_acc zero: float4 stores, 4x unrolled grid-stride
//    - feat->fp16: float4 in (4 floats), uint2 out (4 halves)
//    - degrees + tiny table
__global__ void setup_kernel(const float* __restrict__ feat,
                             const float* __restrict__ embed,
                             const float* __restrict__ Gw,
                             const int* __restrict__ src,
                             const int* __restrict__ dst,
                             int n, int e) {
    int i = blockIdx.x * blockDim.x + threadIdx.x;
    int stride = gridDim.x * blockDim.x;

    // zero g_acc: n*32 float4 slots, unroll 4 (stride pattern keeps coalescing)
    {
        float4* a4 = (float4*)g_acc;
        int tot = n * 32;
        const float4 z = make_float4(0.f, 0.f, 0.f, 0.f);
        int k = i * 4;
        int step = stride * 4;
        for (; k + 3 < tot; k += step) {
            a4[k] = z; a4[k + 1] = z; a4[k + 2] = z; a4[k + 3] = z;
        }
        for (; k < tot; k++) a4[k] = z;
    }

    // feat -> fp16: process 4 floats per iteration
    {
        const float4* f4 = (const float4*)feat;
        uint2* out2 = (uint2*)g_feath;
        int tot = n * 16;   // float4 count
        for (int k = i; k < tot; k += stride) {
            float4 v = f4[k];
            __half2 h0 = __floats2half2_rn(v.x, v.y);
            __half2 h1 = __floats2half2_rn(v.z, v.w);
            uint2 o;
            o.x = *(unsigned*)&h0;
            o.y = *(unsigned*)&h1;
            out2[k] = o;
        }
    }

    for (int k = i; k < n; k += stride) g_accs[k] = 0.f;

    for (int k = i; k < e; k += stride) {
        atomicAdd(&g_din[dst[k]], 1);
        atomicAdd(&g_dout[src[k]], 1);
    }

    for (int t = i; t < NROWS * D; t += stride) {
        int r = t >> 6;
        int d = t & 63;
        float s = 0.f;
#pragma unroll
        for (int k = 0; k < 32; k++)
            s = fmaf(embed[r * 32 + k], Gw[d * 32 + k], s);
        g_t2h[t] = __float2half_rn(s);
    }
}

// ---------------------------------------------------------------------------
// 1) edge kernel: PERSISTENT blocks (single wave), 8 lanes/edge, 32 edges
//    per tile. Table+boundaries staged in smem once per block. O(1) bucket
//    search. d2-only scaling (d0 applied in gemm via linearity).
__global__ void edge_kernel(
        const float2* __restrict__ loc,
        const float* __restrict__ bnd,
        const int* __restrict__ src,
        const int* __restrict__ dst,
        const int* __restrict__ inter,
        int e) {
    __shared__ float sb[NBND];
    __shared__ uint4 ts[NROWS * 8];   // fp16 table rows: 8 uint4 per row

    if (threadIdx.x < NBND) sb[threadIdx.x] = bnd[threadIdx.x];
    {
        const uint4* tg = (const uint4*)g_t2h;
        for (int k = threadIdx.x; k < NROWS * 8; k += 256) ts[k] = tg[k];
    }
    __syncthreads();
    float guess_scale = 63.0f / fmaxf(sb[NBND - 1], 1e-20f);

    int grp   = threadIdx.x >> 3;    // 0..31 edge slot within block
    int sub   = threadIdx.x & 7;
    int lane  = threadIdx.x & 31;
    int base  = lane & 24;

    const unsigned FULL = 0xffffffffu;
    const uint4* f4 = (const uint4*)g_feath;

    int ntiles = (e + 31) >> 5;
    for (int t = blockIdx.x; t < ntiles; t += gridDim.x) {
        int eidx0 = (t << 5) + grp;
        bool valid = (eidx0 < e);
        int eidx = valid ? eidx0 : 0;

        int s = src[eidx];
        int d = dst[eidx];
        int dout = g_dout[s];
        float2 ls = loc[s];

        int id = 0;
        if (sub >= 1 && sub <= 5) id = inter[eidx * 5 + (sub - 1)];

        int bk = 0;
        if (sub < 6) {
            float2 o = (sub == 0) ? loc[d] : loc[id];
            float dx = o.x - ls.x;
            float dy = o.y - ls.y;
            float v = sqrtf(dx * dx + dy * dy);
            // searchsorted(side=left): first k with sb[k] >= v.
            int k = (int)ceilf(v * guess_scale);
            k = min(NBND, max(0, k));
            while (k > 0 && sb[k - 1] >= v) --k;
            while (k < NBND && sb[k] < v) ++k;
            bk = k;
        }

        int bks[6], ids[6];
#pragma unroll
        for (int j = 0; j < 6; j++) bks[j] = __shfl_sync(FULL, bk, base + j);
        ids[0] = s;
#pragma unroll
        for (int j = 1; j < 6; j++) ids[j] = __shfl_sync(FULL, id, base + j);

        uint4 fv[6];
#pragma unroll
        for (int j = 0; j < 6; j++) fv[j] = f4[ids[j] * 8 + sub];

        float4 c0a = make_float4(0.f, 0.f, 0.f, 0.f);
        float4 c0b = make_float4(0.f, 0.f, 0.f, 0.f);
        acc_prod(ts[bks[0] * 8 + sub], fv[0], c0a, c0b);

        float4 c1a = make_float4(0.f, 0.f, 0.f, 0.f);
        float4 c1b = make_float4(0.f, 0.f, 0.f, 0.f);
#pragma unroll
        for (int j = 1; j < 6; j++)
            acc_prod(ts[bks[j] * 8 + sub], fv[j], c1a, c1b);

        float sc = rsqrtf(fmaxf((float)dout, 1.f));
        float m = 0.2f * sc;
        c0a.x *= sc; c0a.y *= sc; c0a.z *= sc; c0a.w *= sc;
        c0b.x *= sc; c0b.y *= sc; c0b.z *= sc; c0b.w *= sc;
        c1a.x *= m;  c1a.y *= m;  c1a.z *= m;  c1a.w *= m;
        c1b.x *= m;  c1b.y *= m;  c1b.z *= m;  c1b.w *= m;

        if (valid) {
            float* p0 = g_acc + d * DD + sub * 8;
            red_add_v4(p0,         c0a);
            red_add_v4(p0 + 4,     c0b);
            red_add_v4(p0 + D,     c1a);
            red_add_v4(p0 + D + 4, c1b);
            if (sub == 0) atomicAdd(&g_accs[d], sc);
        }
    }
}

// ---------------------------------------------------------------------------
// 2) persistent GEMM v3: out = d0 * (acc @ W^T + accs*b).
//    64-node tiles, 8 nodes/warp, LDS.128 W loads (stride 132), LDS.128
//    broadcast A loads. W staged once per block.
#define WKP 132
#define GS_WS   0
#define GS_AS   (D * WKP)
#define GS_SS   (GS_AS + 64 * DD)
#define GS_D0   (GS_SS + 64)
#define GS_BS   (GS_D0 + 64)
#define GS_TOT  ((GS_BS + D) * 4)

__global__ void __launch_bounds__(256) gemm_kernel(
        const float* __restrict__ aggw,
        const float* __restrict__ aggb,
        float* __restrict__ out, int n) {
    extern __shared__ float gsm[];
    float* Ws  = gsm + GS_WS;
    float* As  = gsm + GS_AS;
    float* Ss  = gsm + GS_SS;
    float* D0s = gsm + GS_D0;
    float* Bs  = gsm + GS_BS;

    int tid = threadIdx.x;
    int gi = blockIdx.x * blockDim.x + tid;
    int gstride = gridDim.x * blockDim.x;

    for (int k = gi; k < n; k += gstride) g_dout[k] = 0;

    for (int idx = tid; idx < D * DD; idx += 256) {
        int dd = idx >> 7;
        int k  = idx & 127;
        Ws[dd * WKP + k] = aggw[idx];
    }
    if (tid < D) Bs[tid] = aggb[tid];

    int ntiles = (n + 63) >> 6;
    int w = tid >> 5;
    int l = tid & 31;

    for (int t = blockIdx.x; t < ntiles; t += gridDim.x) {
        int basev = t << 6;
        __syncthreads();
        for (int idx = tid; idx < 64 * 32; idx += 256) {
            int j = idx >> 5;
            int c = idx & 31;
            int node = basev + j;
            float4 v = make_float4(0.f, 0.f, 0.f, 0.f);
            if (node < n) v = ((const float4*)g_acc)[node * 32 + c];
            ((float4*)(As + j * DD))[c] = v;
        }
        if (tid < 64) {
            int node = basev + tid;
            float ssv = 0.f, d0v = 0.f;
            if (node < n) {
                ssv = g_accs[node];
                int din = g_din[node];
                g_din[node] = 0;   // this block owns this node
                d0v = rsqrtf(fmaxf((float)din, 1.f));
            }
            Ss[tid]  = ssv;
            D0s[tid] = d0v;
        }
        __syncthreads();

        const float* wr0 = Ws + l * WKP;
        const float* wr1 = Ws + (l + 32) * WKP;
        const float* ar  = As + (w << 3) * DD;

        unsigned long long acc[8][2];
#pragma unroll
        for (int j = 0; j < 8; j++) { acc[j][0] = 0ull; acc[j][1] = 0ull; }

#pragma unroll 2
        for (int k = 0; k < DD; k += 4) {
            float4 w0 = *(const float4*)(wr0 + k);
            float4 w1 = *(const float4*)(wr1 + k);
            unsigned long long w0lo = *(unsigned long long*)&w0.x;
            unsigned long long w0hi = *(unsigned long long*)&w0.z;
            unsigned long long w1lo = *(unsigned long long*)&w1.x;
            unsigned long long w1hi = *(unsigned long long*)&w1.z;
#pragma unroll
            for (int j = 0; j < 8; j++) {
                float4 a = *(const float4*)(ar + j * DD + k);
                unsigned long long alo = *(unsigned long long*)&a.x;
                unsigned long long ahi = *(unsigned long long*)&a.z;
                fmaf2(acc[j][0], alo, w0lo);
                fmaf2(acc[j][0], ahi, w0hi);
                fmaf2(acc[j][1], alo, w1lo);
                fmaf2(acc[j][1], ahi, w1hi);
            }
        }

#pragma unroll
        for (int j = 0; j < 8; j++) {
            int nd = basev + (w << 3) + j;
            if (nd < n) {
                float d0v = D0s[(w << 3) + j];
                float ss  = Ss[(w << 3) + j];
                float2 q0 = *(float2*)&acc[j][0];
                float2 q1 = *(float2*)&acc[j][1];
                out[nd * D + l]      = d0v * ((q0.x + q0.y) + ss * Bs[l]);
                out[nd * D + l + 32] = d0v * ((q1.x + q1.y) + ss * Bs[l + 32]);
            }
        }
        __syncthreads();
    }
}

// ---------------------------------------------------------------------------
extern "C" void kernel_launch(void* const* d_in, const int* in_sizes, int n_in,
                              void* d_out, int out_size) {
    const float*  feat  = (const float*)d_in[0];
    const float2* loc   = (const float2*)d_in[1];
    const float*  embed = (const float*)d_in[2];
    const float*  Gw    = (const float*)d_in[3];
    const float*  aggw  = (const float*)d_in[4];
    const float*  aggb  = (const float*)d_in[5];
    const float*  bnd   = (const float*)d_in[6];
    const int*    src   = (const int*)d_in[7];
    const int*    dst   = (const int*)d_in[8];
    const int*    inter = (const int*)d_in[9];
    float* out = (float*)d_out;

    int n = in_sizes[0] / D;   // 50000
    int e = in_sizes[7];       // 400000

    cudaFuncSetAttribute(gemm_kernel,
                         cudaFuncAttributeMaxDynamicSharedMemorySize, GS_TOT);

    setup_kernel<<<2048, 256>>>(feat, embed, Gw, src, dst, n, e);
    edge_kernel<<<888, 256>>>(loc, bnd, src, dst, inter, e);   // 148*6: 1 wave
    gemm_kernel<<<444, 256, GS_TOT>>>(aggw, aggb, out, n);     // 148*3: 1 wave
}

// round 14
// speedup vs baseline: 1.0858x; 1.0858x over previous
#include <cuda_runtime.h>
#include <cuda_fp16.h>
#include <math.h>

#define NMAX   50000
#define EMAX   400000
#define D      64
#define DD     128
#define NBND   64
#define NROWS  65

// Device scratch (zero-init at load; replay-deterministic: memset nodes
// re-zero g_acc/g_accs each call, gemm re-zeroes din/dout each call)
__device__ __align__(16) float   g_acc[NMAX * DD];
__device__ float  g_accs[NMAX];
__device__ int    g_din[NMAX];
__device__ int    g_dout[NMAX];
__device__ __align__(16) __half2 g_feath[NMAX * 32];
__device__ __align__(16) __half  g_t2h[NROWS * D];

__device__ __forceinline__ void red_add_v4(float* p, float4 v) {
    asm volatile("red.global.add.v4.f32 [%0], {%1, %2, %3, %4};"
                 :: "l"(p), "f"(v.x), "f"(v.y), "f"(v.z), "f"(v.w)
                 : "memory");
}

__device__ __forceinline__ void fmaf2(unsigned long long& c,
                                      unsigned long long a,
                                      unsigned long long b) {
    asm("fma.rn.f32x2 %0, %1, %2, %0;" : "+l"(c) : "l"(a), "l"(b));
}

__device__ __forceinline__ void acc_prod(uint4 tv, uint4 fv, float4& ca, float4& cb) {
    const __half2* th = (const __half2*)&tv;
    const __half2* fh = (const __half2*)&fv;
    float2 t0 = __half22float2(th[0]), f0 = __half22float2(fh[0]);
    float2 t1 = __half22float2(th[1]), f1 = __half22float2(fh[1]);
    float2 t2 = __half22float2(th[2]), f2 = __half22float2(fh[2]);
    float2 t3 = __half22float2(th[3]), f3 = __half22float2(fh[3]);
    ca.x = fmaf(t0.x, f0.x, ca.x); ca.y = fmaf(t0.y, f0.y, ca.y);
    ca.z = fmaf(t1.x, f1.x, ca.z); ca.w = fmaf(t1.y, f1.y, ca.w);
    cb.x = fmaf(t2.x, f2.x, cb.x); cb.y = fmaf(t2.y, f2.y, cb.y);
    cb.z = fmaf(t3.x, f3.x, cb.z); cb.w = fmaf(t3.y, f3.y, cb.w);
}

// ---------------------------------------------------------------------------
// 0) setup: convert feat->fp16, degrees, fused table (zeroing via memsets).
__global__ void setup_kernel(const float* __restrict__ feat,
                             const float* __restrict__ embed,
                             const float* __restrict__ Gw,
                             const int* __restrict__ src,
                             const int* __restrict__ dst,
                             int n, int e) {
    int i = blockIdx.x * blockDim.x + threadIdx.x;
    int stride = gridDim.x * blockDim.x;

    int toth = n * 32;
    for (int k = i; k < toth; k += stride) {
        float2 v = ((const float2*)feat)[k];
        g_feath[k] = __floats2half2_rn(v.x, v.y);
    }
    for (int k = i; k < e; k += stride) {
        atomicAdd(&g_din[dst[k]], 1);
        atomicAdd(&g_dout[src[k]], 1);
    }
    for (int t = i; t < NROWS * D; t += stride) {
        int r = t >> 6;
        int d = t & 63;
        float s = 0.f;
#pragma unroll
        for (int k = 0; k < 32; k++)
            s = fmaf(embed[r * 32 + k], Gw[d * 32 + k], s);
        g_t2h[t] = __float2half_rn(s);
    }
}

// ---------------------------------------------------------------------------
// 1) edge kernel: PERSISTENT blocks, 8 lanes/edge, 32 edges per tile.
//    Table+boundaries staged in smem once per block. O(1) bucket search.
//    d2-only scaling (d0 applied in gemm via linearity).
__global__ void edge_kernel(
        const float2* __restrict__ loc,
        const float* __restrict__ bnd,
        const int* __restrict__ src,
        const int* __restrict__ dst,
        const int* __restrict__ inter,
        int e) {
    __shared__ float sb[NBND];
    __shared__ uint4 ts[NROWS * 8];   // fp16 table rows: 8 uint4 per row

    if (threadIdx.x < NBND) sb[threadIdx.x] = bnd[threadIdx.x];
    {
        const uint4* tg = (const uint4*)g_t2h;
        for (int k = threadIdx.x; k < NROWS * 8; k += 256) ts[k] = tg[k];
    }
    __syncthreads();
    float guess_scale = 63.0f / fmaxf(sb[NBND - 1], 1e-20f);

    int grp   = threadIdx.x >> 3;    // 0..31 edge slot within block
    int sub   = threadIdx.x & 7;
    int lane  = threadIdx.x & 31;
    int base  = lane & 24;

    const unsigned FULL = 0xffffffffu;
    const uint4* f4 = (const uint4*)g_feath;

    int ntiles = (e + 31) >> 5;
    for (int t = blockIdx.x; t < ntiles; t += gridDim.x) {
        int eidx0 = (t << 5) + grp;
        bool valid = (eidx0 < e);
        int eidx = valid ? eidx0 : 0;

        int s = src[eidx];
        int d = dst[eidx];
        int dout = g_dout[s];
        float2 ls = loc[s];

        int id = 0;
        if (sub >= 1 && sub <= 5) id = inter[eidx * 5 + (sub - 1)];

        int bk = 0;
        if (sub < 6) {
            float2 o = (sub == 0) ? loc[d] : loc[id];
            float dx = o.x - ls.x;
            float dy = o.y - ls.y;
            float v = sqrtf(dx * dx + dy * dy);
            // searchsorted(side=left): first k with sb[k] >= v.
            int k = (int)ceilf(v * guess_scale);
            k = min(NBND, max(0, k));
            while (k > 0 && sb[k - 1] >= v) --k;
            while (k < NBND && sb[k] < v) ++k;
            bk = k;
        }

        int bks[6], ids[6];
#pragma unroll
        for (int j = 0; j < 6; j++) bks[j] = __shfl_sync(FULL, bk, base + j);
        ids[0] = s;
#pragma unroll
        for (int j = 1; j < 6; j++) ids[j] = __shfl_sync(FULL, id, base + j);

        uint4 fv[6];
#pragma unroll
        for (int j = 0; j < 6; j++) fv[j] = f4[ids[j] * 8 + sub];

        float4 c0a = make_float4(0.f, 0.f, 0.f, 0.f);
        float4 c0b = make_float4(0.f, 0.f, 0.f, 0.f);
        acc_prod(ts[bks[0] * 8 + sub], fv[0], c0a, c0b);

        float4 c1a = make_float4(0.f, 0.f, 0.f, 0.f);
        float4 c1b = make_float4(0.f, 0.f, 0.f, 0.f);
#pragma unroll
        for (int j = 1; j < 6; j++)
            acc_prod(ts[bks[j] * 8 + sub], fv[j], c1a, c1b);

        float sc = rsqrtf(fmaxf((float)dout, 1.f));
        float m = 0.2f * sc;
        c0a.x *= sc; c0a.y *= sc; c0a.z *= sc; c0a.w *= sc;
        c0b.x *= sc; c0b.y *= sc; c0b.z *= sc; c0b.w *= sc;
        c1a.x *= m;  c1a.y *= m;  c1a.z *= m;  c1a.w *= m;
        c1b.x *= m;  c1b.y *= m;  c1b.z *= m;  c1b.w *= m;

        if (valid) {
            float* p0 = g_acc + d * DD + sub * 8;
            red_add_v4(p0,         c0a);
            red_add_v4(p0 + 4,     c0b);
            red_add_v4(p0 + D,     c1a);
            red_add_v4(p0 + D + 4, c1b);
            if (sub == 0) atomicAdd(&g_accs[d], sc);
        }
    }
}

// ---------------------------------------------------------------------------
// 2) persistent GEMM v3: out = d0 * (acc @ W^T + accs*b).
//    64-node tiles, 8 nodes/warp, LDS.128 W loads (stride 132), LDS.128
//    broadcast A loads. W staged once per block.
#define WKP 132
#define GS_WS   0
#define GS_AS   (D * WKP)
#define GS_SS   (GS_AS + 64 * DD)
#define GS_D0   (GS_SS + 64)
#define GS_BS   (GS_D0 + 64)
#define GS_TOT  ((GS_BS + D) * 4)

__global__ void __launch_bounds__(256) gemm_kernel(
        const float* __restrict__ aggw,
        const float* __restrict__ aggb,
        float* __restrict__ out, int n) {
    extern __shared__ float gsm[];
    float* Ws  = gsm + GS_WS;
    float* As  = gsm + GS_AS;
    float* Ss  = gsm + GS_SS;
    float* D0s = gsm + GS_D0;
    float* Bs  = gsm + GS_BS;

    int tid = threadIdx.x;
    int gi = blockIdx.x * blockDim.x + tid;
    int gstride = gridDim.x * blockDim.x;

    for (int k = gi; k < n; k += gstride) g_dout[k] = 0;

    for (int idx = tid; idx < D * DD; idx += 256) {
        int dd = idx >> 7;
        int k  = idx & 127;
        Ws[dd * WKP + k] = aggw[idx];
    }
    if (tid < D) Bs[tid] = aggb[tid];

    int ntiles = (n + 63) >> 6;
    int w = tid >> 5;
    int l = tid & 31;

    for (int t = blockIdx.x; t < ntiles; t += gridDim.x) {
        int basev = t << 6;
        __syncthreads();
        for (int idx = tid; idx < 64 * 32; idx += 256) {
            int j = idx >> 5;
            int c = idx & 31;
            int node = basev + j;
            float4 v = make_float4(0.f, 0.f, 0.f, 0.f);
            if (node < n) v = ((const float4*)g_acc)[node * 32 + c];
            ((float4*)(As + j * DD))[c] = v;
        }
        if (tid < 64) {
            int node = basev + tid;
            float ssv = 0.f, d0v = 0.f;
            if (node < n) {
                ssv = g_accs[node];
                int din = g_din[node];
                g_din[node] = 0;   // this block owns this node
                d0v = rsqrtf(fmaxf((float)din, 1.f));
            }
            Ss[tid]  = ssv;
            D0s[tid] = d0v;
        }
        __syncthreads();

        const float* wr0 = Ws + l * WKP;
        const float* wr1 = Ws + (l + 32) * WKP;
        const float* ar  = As + (w << 3) * DD;

        unsigned long long acc[8][2];
#pragma unroll
        for (int j = 0; j < 8; j++) { acc[j][0] = 0ull; acc[j][1] = 0ull; }

#pragma unroll 2
        for (int k = 0; k < DD; k += 4) {
            float4 w0 = *(const float4*)(wr0 + k);
            float4 w1 = *(const float4*)(wr1 + k);
            unsigned long long w0lo = *(unsigned long long*)&w0.x;
            unsigned long long w0hi = *(unsigned long long*)&w0.z;
            unsigned long long w1lo = *(unsigned long long*)&w1.x;
            unsigned long long w1hi = *(unsigned long long*)&w1.z;
#pragma unroll
            for (int j = 0; j < 8; j++) {
                float4 a = *(const float4*)(ar + j * DD + k);
                unsigned long long alo = *(unsigned long long*)&a.x;
                unsigned long long ahi = *(unsigned long long*)&a.z;
                fmaf2(acc[j][0], alo, w0lo);
                fmaf2(acc[j][0], ahi, w0hi);
                fmaf2(acc[j][1], alo, w1lo);
                fmaf2(acc[j][1], ahi, w1hi);
            }
        }

#pragma unroll
        for (int j = 0; j < 8; j++) {
            int nd = basev + (w << 3) + j;
            if (nd < n) {
                float d0v = D0s[(w << 3) + j];
                float ss  = Ss[(w << 3) + j];
                float2 q0 = *(float2*)&acc[j][0];
                float2 q1 = *(float2*)&acc[j][1];
                out[nd * D + l]      = d0v * ((q0.x + q0.y) + ss * Bs[l]);
                out[nd * D + l + 32] = d0v * ((q1.x + q1.y) + ss * Bs[l + 32]);
            }
        }
        __syncthreads();
    }
}

// ---------------------------------------------------------------------------
extern "C" void kernel_launch(void* const* d_in, const int* in_sizes, int n_in,
                              void* d_out, int out_size) {
    const float*  feat  = (const float*)d_in[0];
    const float2* loc   = (const float2*)d_in[1];
    const float*  embed = (const float*)d_in[2];
    const float*  Gw    = (const float*)d_in[3];
    const float*  aggw  = (const float*)d_in[4];
    const float*  aggb  = (const float*)d_in[5];
    const float*  bnd   = (const float*)d_in[6];
    const int*    src   = (const int*)d_in[7];
    const int*    dst   = (const int*)d_in[8];
    const int*    inter = (const int*)d_in[9];
    float* out = (float*)d_out;

    int n = in_sizes[0] / D;   // 50000
    int e = in_sizes[7];       // 400000

    cudaFuncSetAttribute(gemm_kernel,
                         cudaFuncAttributeMaxDynamicSharedMemorySize, GS_TOT);

    // zero accumulators via memset nodes (graph-capturable, no SM issue cost)
    void* accp = nullptr;
    void* accsp = nullptr;
    cudaGetSymbolAddress(&accp, g_acc);
    cudaGetSymbolAddress(&accsp, g_accs);
    cudaMemsetAsync(accp, 0, (size_t)NMAX * DD * sizeof(float), 0);
    cudaMemsetAsync(accsp, 0, (size_t)NMAX * sizeof(float), 0);

    setup_kernel<<<4096, 256>>>(feat, embed, Gw, src, dst, n, e);
    edge_kernel<<<1184, 256>>>(loc, bnd, src, dst, inter, e);
    gemm_kernel<<<444, 256, GS_TOT>>>(aggw, aggb, out, n);
}

// round 15
// speedup vs baseline: 1.1400x; 1.0500x over previous
#include <cuda_runtime.h>
#include <cuda_fp16.h>
#include <math.h>

#define NMAX   50000
#define EMAX   400000
#define D      64
#define DD     128
#define NBND   64
#define NROWS  65

// Device scratch (zero-init at load; replay-deterministic: setup re-zeroes
// g_acc/g_accs each call, gemm re-zeroes din/dout each call)
__device__ __align__(16) float   g_acc[NMAX * DD];
__device__ float  g_accs[NMAX];
__device__ int    g_din[NMAX];
__device__ int    g_dout[NMAX];
__device__ __align__(16) __half2 g_feath[NMAX * 32];
__device__ __align__(16) __half  g_t2h[NROWS * D];

__device__ __forceinline__ void red_add_v4(float* p, float4 v) {
    asm volatile("red.global.add.v4.f32 [%0], {%1, %2, %3, %4};"
                 :: "l"(p), "f"(v.x), "f"(v.y), "f"(v.z), "f"(v.w)
                 : "memory");
}

__device__ __forceinline__ void fmaf2(unsigned long long& c,
                                      unsigned long long a,
                                      unsigned long long b) {
    asm("fma.rn.f32x2 %0, %1, %2, %0;" : "+l"(c) : "l"(a), "l"(b));
}

__device__ __forceinline__ void acc_prod(uint4 tv, uint4 fv, float4& ca, float4& cb) {
    const __half2* th = (const __half2*)&tv;
    const __half2* fh = (const __half2*)&fv;
    float2 t0 = __half22float2(th[0]), f0 = __half22float2(fh[0]);
    float2 t1 = __half22float2(th[1]), f1 = __half22float2(fh[1]);
    float2 t2 = __half22float2(th[2]), f2 = __half22float2(fh[2]);
    float2 t3 = __half22float2(th[3]), f3 = __half22float2(fh[3]);
    ca.x = fmaf(t0.x, f0.x, ca.x); ca.y = fmaf(t0.y, f0.y, ca.y);
    ca.z = fmaf(t1.x, f1.x, ca.z); ca.w = fmaf(t1.y, f1.y, ca.w);
    cb.x = fmaf(t2.x, f2.x, cb.x); cb.y = fmaf(t2.y, f2.y, cb.y);
    cb.z = fmaf(t3.x, f3.x, cb.z); cb.w = fmaf(t3.y, f3.y, cb.w);
}

// ---------------------------------------------------------------------------
// 0) setup: zero accumulators, convert feat->fp16, degrees, fused table.
//    (R12 version — zero loop overlaps the other setup work.)
__global__ void setup_kernel(const float* __restrict__ feat,
                             const float* __restrict__ embed,
                             const float* __restrict__ Gw,
                             const int* __restrict__ src,
                             const int* __restrict__ dst,
                             int n, int e) {
    int i = blockIdx.x * blockDim.x + threadIdx.x;
    int stride = gridDim.x * blockDim.x;

    int tot4 = n * (DD / 4);
    float4 z = make_float4(0.f, 0.f, 0.f, 0.f);
    for (int k = i; k < tot4; k += stride) ((float4*)g_acc)[k] = z;
    for (int k = i; k < n; k += stride) g_accs[k] = 0.f;

    int toth = n * 32;
    for (int k = i; k < toth; k += stride) {
        float2 v = ((const float2*)feat)[k];
        g_feath[k] = __floats2half2_rn(v.x, v.y);
    }
    for (int k = i; k < e; k += stride) {
        atomicAdd(&g_din[dst[k]], 1);
        atomicAdd(&g_dout[src[k]], 1);
    }
    for (int t = i; t < NROWS * D; t += stride) {
        int r = t >> 6;
        int d = t & 63;
        float s = 0.f;
#pragma unroll
        for (int k = 0; k < 32; k++)
            s = fmaf(embed[r * 32 + k], Gw[d * 32 + k], s);
        g_t2h[t] = __float2half_rn(s);
    }
}

// ---------------------------------------------------------------------------
// 1) edge kernel: PERSISTENT blocks, 8 lanes/edge, 32 edges per tile,
//    SOFTWARE-PIPELINED: next tile's index/scalar loads are issued before
//    the current tile's REDs (whose "memory" clobber otherwise fences them).
__global__ void edge_kernel(
        const float2* __restrict__ loc,
        const float* __restrict__ bnd,
        const int* __restrict__ src,
        const int* __restrict__ dst,
        const int* __restrict__ inter,
        int e) {
    __shared__ float sb[NBND];
    __shared__ uint4 ts[NROWS * 8];   // fp16 table rows: 8 uint4 per row

    if (threadIdx.x < NBND) sb[threadIdx.x] = bnd[threadIdx.x];
    {
        const uint4* tg = (const uint4*)g_t2h;
        for (int k = threadIdx.x; k < NROWS * 8; k += 256) ts[k] = tg[k];
    }
    __syncthreads();
    float guess_scale = 63.0f / fmaxf(sb[NBND - 1], 1e-20f);

    int grp   = threadIdx.x >> 3;    // 0..31 edge slot within block
    int sub   = threadIdx.x & 7;
    int lane  = threadIdx.x & 31;
    int base  = lane & 24;

    const unsigned FULL = 0xffffffffu;
    const uint4* f4 = (const uint4*)g_feath;

    int ntiles = (e + 31) >> 5;
    int gstep = gridDim.x;

    // ---- prologue: load tile state for the first tile ----
    int cS = 0, cD = 0, cId = 0, cDout = 0;
    float2 cLs = make_float2(0.f, 0.f), cLo = make_float2(0.f, 0.f);
    bool cValid = false;
    {
        int t0 = blockIdx.x;
        if (t0 < ntiles) {
            int ei0 = (t0 << 5) + grp;
            cValid = (ei0 < e);
            int ei = cValid ? ei0 : 0;
            cS = src[ei];
            cD = dst[ei];
            cId = 0;
            if (sub >= 1 && sub <= 5) cId = inter[ei * 5 + (sub - 1)];
            cDout = g_dout[cS];
            cLs = loc[cS];
            cLo = (sub == 0) ? loc[cD] : loc[cId];
        }
    }

    for (int t = blockIdx.x; t < ntiles; t += gstep) {
        // ---- compute bucket from prefetched state ----
        int bk = 0;
        if (sub < 6) {
            float dx = cLo.x - cLs.x;
            float dy = cLo.y - cLs.y;
            float v = sqrtf(dx * dx + dy * dy);
            int k = (int)ceilf(v * guess_scale);
            k = min(NBND, max(0, k));
            while (k > 0 && sb[k - 1] >= v) --k;
            while (k < NBND && sb[k] < v) ++k;
            bk = k;
        }

        int bks[6], ids[6];
#pragma unroll
        for (int j = 0; j < 6; j++) bks[j] = __shfl_sync(FULL, bk, base + j);
        ids[0] = cS;
#pragma unroll
        for (int j = 1; j < 6; j++) ids[j] = __shfl_sync(FULL, cId, base + j);

        uint4 fv[6];
#pragma unroll
        for (int j = 0; j < 6; j++) fv[j] = f4[ids[j] * 8 + sub];

        float4 c0a = make_float4(0.f, 0.f, 0.f, 0.f);
        float4 c0b = make_float4(0.f, 0.f, 0.f, 0.f);
        acc_prod(ts[bks[0] * 8 + sub], fv[0], c0a, c0b);

        float4 c1a = make_float4(0.f, 0.f, 0.f, 0.f);
        float4 c1b = make_float4(0.f, 0.f, 0.f, 0.f);
#pragma unroll
        for (int j = 1; j < 6; j++)
            acc_prod(ts[bks[j] * 8 + sub], fv[j], c1a, c1b);

        float sc = rsqrtf(fmaxf((float)cDout, 1.f));
        float m = 0.2f * sc;
        c0a.x *= sc; c0a.y *= sc; c0a.z *= sc; c0a.w *= sc;
        c0b.x *= sc; c0b.y *= sc; c0b.z *= sc; c0b.w *= sc;
        c1a.x *= m;  c1a.y *= m;  c1a.z *= m;  c1a.w *= m;
        c1b.x *= m;  c1b.y *= m;  c1b.z *= m;  c1b.w *= m;

        int outD = cD;
        bool outValid = cValid;

        // ---- prefetch next tile's state BEFORE the REDs ----
        int nt = t + gstep;
        if (nt < ntiles) {
            int ei0 = (nt << 5) + grp;
            bool v2 = (ei0 < e);
            int ei = v2 ? ei0 : 0;
            int nS = src[ei];
            int nD = dst[ei];
            int nId = 0;
            if (sub >= 1 && sub <= 5) nId = inter[ei * 5 + (sub - 1)];
            int nDout = g_dout[nS];
            float2 nLs = loc[nS];
            float2 nLo = (sub == 0) ? loc[nD] : loc[nId];
            cS = nS; cD = nD; cId = nId; cDout = nDout;
            cLs = nLs; cLo = nLo; cValid = v2;
        }

        // ---- scatter ----
        if (outValid) {
            float* p0 = g_acc + outD * DD + sub * 8;
            red_add_v4(p0,         c0a);
            red_add_v4(p0 + 4,     c0b);
            red_add_v4(p0 + D,     c1a);
            red_add_v4(p0 + D + 4, c1b);
            if (sub == 0) atomicAdd(&g_accs[outD], sc);
        }
    }
}

// ---------------------------------------------------------------------------
// 2) persistent GEMM v3: out = d0 * (acc @ W^T + accs*b).
//    64-node tiles, 8 nodes/warp, LDS.128 W loads (stride 132), LDS.128
//    broadcast A loads. W staged once per block.
#define WKP 132
#define GS_WS   0
#define GS_AS   (D * WKP)
#define GS_SS   (GS_AS + 64 * DD)
#define GS_D0   (GS_SS + 64)
#define GS_BS   (GS_D0 + 64)
#define GS_TOT  ((GS_BS + D) * 4)

__global__ void __launch_bounds__(256) gemm_kernel(
        const float* __restrict__ aggw,
        const float* __restrict__ aggb,
        float* __restrict__ out, int n) {
    extern __shared__ float gsm[];
    float* Ws  = gsm + GS_WS;
    float* As  = gsm + GS_AS;
    float* Ss  = gsm + GS_SS;
    float* D0s = gsm + GS_D0;
    float* Bs  = gsm + GS_BS;

    int tid = threadIdx.x;
    int gi = blockIdx.x * blockDim.x + tid;
    int gstride = gridDim.x * blockDim.x;

    for (int k = gi; k < n; k += gstride) g_dout[k] = 0;

    for (int idx = tid; idx < D * DD; idx += 256) {
        int dd = idx >> 7;
        int k  = idx & 127;
        Ws[dd * WKP + k] = aggw[idx];
    }
    if (tid < D) Bs[tid] = aggb[tid];

    int ntiles = (n + 63) >> 6;
    int w = tid >> 5;
    int l = tid & 31;

    for (int t = blockIdx.x; t < ntiles; t += gridDim.x) {
        int basev = t << 6;
        __syncthreads();
        for (int idx = tid; idx < 64 * 32; idx += 256) {
            int j = idx >> 5;
            int c = idx & 31;
            int node = basev + j;
            float4 v = make_float4(0.f, 0.f, 0.f, 0.f);
            if (node < n) v = ((const float4*)g_acc)[node * 32 + c];
            ((float4*)(As + j * DD))[c] = v;
        }
        if (tid < 64) {
            int node = basev + tid;
            float ssv = 0.f, d0v = 0.f;
            if (node < n) {
                ssv = g_accs[node];
                int din = g_din[node];
                g_din[node] = 0;   // this block owns this node
                d0v = rsqrtf(fmaxf((float)din, 1.f));
            }
            Ss[tid]  = ssv;
            D0s[tid] = d0v;
        }
        __syncthreads();

        const float* wr0 = Ws + l * WKP;
        const float* wr1 = Ws + (l + 32) * WKP;
        const float* ar  = As + (w << 3) * DD;

        unsigned long long acc[8][2];
#pragma unroll
        for (int j = 0; j < 8; j++) { acc[j][0] = 0ull; acc[j][1] = 0ull; }

#pragma unroll 2
        for (int k = 0; k < DD; k += 4) {
            float4 w0 = *(const float4*)(wr0 + k);
            float4 w1 = *(const float4*)(wr1 + k);
            unsigned long long w0lo = *(unsigned long long*)&w0.x;
            unsigned long long w0hi = *(unsigned long long*)&w0.z;
            unsigned long long w1lo = *(unsigned long long*)&w1.x;
            unsigned long long w1hi = *(unsigned long long*)&w1.z;
#pragma unroll
            for (int j = 0; j < 8; j++) {
                float4 a = *(const float4*)(ar + j * DD + k);
                unsigned long long alo = *(unsigned long long*)&a.x;
                unsigned long long ahi = *(unsigned long long*)&a.z;
                fmaf2(acc[j][0], alo, w0lo);
                fmaf2(acc[j][0], ahi, w0hi);
                fmaf2(acc[j][1], alo, w1lo);
                fmaf2(acc[j][1], ahi, w1hi);
            }
        }

#pragma unroll
        for (int j = 0; j < 8; j++) {
            int nd = basev + (w << 3) + j;
            if (nd < n) {
                float d0v = D0s[(w << 3) + j];
                float ss  = Ss[(w << 3) + j];
                float2 q0 = *(float2*)&acc[j][0];
                float2 q1 = *(float2*)&acc[j][1];
                out[nd * D + l]      = d0v * ((q0.x + q0.y) + ss * Bs[l]);
                out[nd * D + l + 32] = d0v * ((q1.x + q1.y) + ss * Bs[l + 32]);
            }
        }
        __syncthreads();
    }
}

// ---------------------------------------------------------------------------
extern "C" void kernel_launch(void* const* d_in, const int* in_sizes, int n_in,
                              void* d_out, int out_size) {
    const float*  feat  = (const float*)d_in[0];
    const float2* loc   = (const float2*)d_in[1];
    const float*  embed = (const float*)d_in[2];
    const float*  Gw    = (const float*)d_in[3];
    const float*  aggw  = (const float*)d_in[4];
    const float*  aggb  = (const float*)d_in[5];
    const float*  bnd   = (const float*)d_in[6];
    const int*    src   = (const int*)d_in[7];
    const int*    dst   = (const int*)d_in[8];
    const int*    inter = (const int*)d_in[9];
    float* out = (float*)d_out;

    int n = in_sizes[0] / D;   // 50000
    int e = in_sizes[7];       // 400000

    cudaFuncSetAttribute(gemm_kernel,
                         cudaFuncAttributeMaxDynamicSharedMemorySize, GS_TOT);

    setup_kernel<<<4096, 256>>>(feat, embed, Gw, src, dst, n, e);
    edge_kernel<<<1184, 256>>>(loc, bnd, src, dst, inter, e);
    gemm_kernel<<<444, 256, GS_TOT>>>(aggw, aggb, out, n);
}